// round 7
// baseline (speedup 1.0000x reference)
#include <cuda_runtime.h>
#include <cuda_fp16.h>
#include <cstdint>
#include <cstddef>

// FixedGraphAttentionLayer: bs=4, L=20000, D=16, Fin=Fout=128
//   y = x @ W per node (linear rewrite), y stored fp16.
//   e[b,l,d] = s1[adj[b,l,d]] + s2[adj[b,l,0]]  (scores from fp32 accumulators)
// k1 = HMMA (mma.sync m16n8k16 f16f16f32) GEMM + fused scores.
// prep (wide grid) = adj dtype detect + W fragment pre-pack.
// k2 = softmax + LDG.128 gather (half-warps on alternate neighbor rows).

#define LRELU_ALPHA 0.2f
static constexpr int BS = 4;
static constexpr int L  = 20000;
static constexpr int D  = 16;
static constexpr int F  = 128;
static constexpr int NROWS = BS * L;   // 80000

__device__ __align__(16) __half g_yh[(size_t)NROWS * F];   // 20.5 MB
__device__ float g_s1[NROWS];
__device__ float g_s2[NROWS];
__device__ int   g_adj_is64;
__device__ __align__(16) uint2 g_Bpack[8 * 16 * 32];       // [kc][nt][lane], 32 KB

// ---------------------------------------------------------------------------
// Prep (32 blocks x 128 threads; one fragment element per thread):
// adj dtype detect (int64 iff odd 32-bit words all zero; values < 2^31)
// + pack W (fp32 [k=128][n=128]) into mma.m16n8k16 B fragments (fp16).
//   b0 = {W[k0][n], W[k0+1][n]}, b1 = {W[k0+8][n], W[k0+9][n]},
//   k0 = 16*kc + tg*2, n = 8*nt + g   (g = lane>>2, tg = lane&3)
// ---------------------------------------------------------------------------
__global__ void prep_kernel(const int* __restrict__ adj32,
                            const float* __restrict__ W)
{
    const int t = threadIdx.x;
    if (blockIdx.x == 0 && t < 32) {
        const int bad = (adj32[2 * t + 1] != 0) | (adj32[2 * t + 65] != 0);
        const unsigned m = __ballot_sync(0xffffffffu, bad);
        if (t == 0) g_adj_is64 = (m == 0u);
    }
    const int e = blockIdx.x * 128 + t;            // 0..4095
    const int kc = e >> 9, nt = (e >> 5) & 15, lane = e & 31;
    const int g = lane >> 2, tg = lane & 3;
    const int n = nt * 8 + g, k0 = kc * 16 + tg * 2;
    __half2 b0 = __floats2half2_rn(W[k0 * F + n],       W[(k0 + 1) * F + n]);
    __half2 b1 = __floats2half2_rn(W[(k0 + 8) * F + n], W[(k0 + 9) * F + n]);
    uint2 u;
    u.x = *reinterpret_cast<unsigned*>(&b0);
    u.y = *reinterpret_cast<unsigned*>(&b1);
    g_Bpack[e] = u;
}

// ---------------------------------------------------------------------------
// Kernel 1: y = x @ W via HMMA + fused scores. 128 threads, 64 rows/block.
// Warp w owns rows w*16..w*16+15, all 128 cols (16 n-tiles x 8 k-chunks).
// x tile staged fp16 in smem with XOR swizzle (bank-conflict-free frag loads).
// ---------------------------------------------------------------------------
__global__ __launch_bounds__(128)
void gemm_scores_kernel(const float* __restrict__ x,
                        const float* __restrict__ a)
{
    __shared__ __half2 Xs[64 * 64];   // 16 KB: [row][kh2], kh2 swizzled ^(row&7)*4
    __shared__ uint2   Bs[4096];      // 32 KB: [kc][nt][lane]

    const int tid  = threadIdx.x;
    const int lane = tid & 31;
    const int w    = tid >> 5;
    const int g    = lane >> 2;       // 0..7
    const int tg   = lane & 3;        // 0..3
    const int rowbase = blockIdx.x * 64;

    // copy B fragments (32 KB) global -> smem, coalesced
    {
        const uint4* src = (const uint4*)g_Bpack;
        uint4*       dst = (uint4*)Bs;
        #pragma unroll
        for (int i = tid; i < 2048; i += 128) dst[i] = src[i];
    }
    // load x tile (64x128 fp32) -> fp16 swizzled smem
    #pragma unroll
    for (int j = tid; j < 4096; j += 128) {
        const int r = j >> 6, kh2 = j & 63;
        float2 v = *(const float2*)(x + (size_t)(rowbase + r) * F + kh2 * 2);
        Xs[r * 64 + (kh2 ^ ((r & 7) * 4))] = __floats2half2_rn(v.x, v.y);
    }
    __syncthreads();

    // A fragments for this warp's 16 rows, all 8 k-chunks (32 regs)
    unsigned Areg[8][4];
    {
        const int r0 = w * 16 + g, r1 = r0 + 8;
        const int s  = g * 4;
        #pragma unroll
        for (int kc = 0; kc < 8; kc++) {
            const int kl = kc * 8 + tg, kh = kl + 4;
            Areg[kc][0] = *reinterpret_cast<unsigned*>(&Xs[r0 * 64 + (kl ^ s)]);
            Areg[kc][1] = *reinterpret_cast<unsigned*>(&Xs[r1 * 64 + (kl ^ s)]);
            Areg[kc][2] = *reinterpret_cast<unsigned*>(&Xs[r0 * 64 + (kh ^ s)]);
            Areg[kc][3] = *reinterpret_cast<unsigned*>(&Xs[r1 * 64 + (kh ^ s)]);
        }
    }

    float acc[16][4];
    #pragma unroll
    for (int nt = 0; nt < 16; nt++)
        #pragma unroll
        for (int q = 0; q < 4; q++) acc[nt][q] = 0.f;

    #pragma unroll
    for (int nt = 0; nt < 16; nt++) {
        #pragma unroll
        for (int kc = 0; kc < 8; kc++) {
            const uint2 b = Bs[kc * 512 + nt * 32 + lane];
            asm volatile(
                "mma.sync.aligned.m16n8k16.row.col.f32.f16.f16.f32 "
                "{%0,%1,%2,%3}, {%4,%5,%6,%7}, {%8,%9}, {%0,%1,%2,%3};"
                : "+f"(acc[nt][0]), "+f"(acc[nt][1]), "+f"(acc[nt][2]), "+f"(acc[nt][3])
                : "r"(Areg[kc][0]), "r"(Areg[kc][1]), "r"(Areg[kc][2]), "r"(Areg[kc][3]),
                  "r"(b.x), "r"(b.y));
        }
    }

    // scores from fp32 accumulators: rows g (p1a/p2a) and g+8 (p1b/p2b)
    float p1a = 0.f, p1b = 0.f, p2a = 0.f, p2b = 0.f;
    #pragma unroll
    for (int nt = 0; nt < 16; nt++) {
        const float2 a1p = *(const float2*)(a + nt * 8 + tg * 2);
        const float2 a2p = *(const float2*)(a + F + nt * 8 + tg * 2);
        p1a += acc[nt][0] * a1p.x + acc[nt][1] * a1p.y;
        p1b += acc[nt][2] * a1p.x + acc[nt][3] * a1p.y;
        p2a += acc[nt][0] * a2p.x + acc[nt][1] * a2p.y;
        p2b += acc[nt][2] * a2p.x + acc[nt][3] * a2p.y;
    }
    #pragma unroll
    for (int o = 1; o <= 2; o <<= 1) {   // reduce over tg quad (lanes g*4..g*4+3)
        p1a += __shfl_xor_sync(0xffffffffu, p1a, o);
        p1b += __shfl_xor_sync(0xffffffffu, p1b, o);
        p2a += __shfl_xor_sync(0xffffffffu, p2a, o);
        p2b += __shfl_xor_sync(0xffffffffu, p2b, o);
    }
    if (tg == 0) {
        const int r = rowbase + w * 16 + g;
        g_s1[r] = p1a;  g_s2[r] = p2a;
        g_s1[r + 8] = p1b;  g_s2[r + 8] = p2b;
    }

    // stage y (fp16) back into Xs with the same swizzle, then coalesced store
    __syncthreads();
    {
        const int r0 = w * 16 + g;
        const int s  = g * 4;
        #pragma unroll
        for (int nt = 0; nt < 16; nt++) {
            const int c = nt * 4 + tg;
            Xs[r0 * 64 + (c ^ s)]       = __floats2half2_rn(acc[nt][0], acc[nt][1]);
            Xs[(r0 + 8) * 64 + (c ^ s)] = __floats2half2_rn(acc[nt][2], acc[nt][3]);
        }
    }
    __syncthreads();
    {
        const int r = tid >> 1;                 // 2 threads per row
        const int s = (r & 7) * 4;
        const int base = (tid & 1) * 32;        // half2 offset
        __half* dst = g_yh + (size_t)(rowbase + r) * F + base * 2;
        #pragma unroll
        for (int j = 0; j < 8; j++) {
            uint4 v = *reinterpret_cast<uint4*>(&Xs[r * 64 + ((base + j * 4) ^ s)]);
            *reinterpret_cast<uint4*>(dst + j * 8) = v;
        }
    }
}

// ---------------------------------------------------------------------------
// Kernel 2: one warp per node. softmax(leaky_relu(e)) over D=16, then
// LDG.128 gather: half-warp h takes neighbor rows d = 2*it + h, lanes li=0..15
// each cover 8 cols (16 B). Merge halves with one shfl_xor(16). fp32 accum.
// ---------------------------------------------------------------------------
__global__ __launch_bounds__(256)
void attn_out_kernel(const int* __restrict__ adj32,
                     float* __restrict__ out)
{
    const int warp = (blockIdx.x * blockDim.x + threadIdx.x) >> 5;
    const int lane = threadIdx.x & 31;
    if (warp >= NROWS) return;

    const int b = warp / L;
    const size_t nodebase = (size_t)b * L;
    const int is64 = g_adj_is64;

    int   idx = 0;
    float e   = -INFINITY;
    if (lane < D) {
        const size_t ei = (size_t)warp * D + lane;
        int raw;
        if (is64) {
            long long v = ((const long long*)adj32)[ei];   // single LDG.64
            raw = (int)v;
        } else {
            raw = adj32[ei];
        }
        raw = raw < 0 ? 0 : (raw >= L ? L - 1 : raw); // defensive clamp
        idx = raw;
        e   = g_s1[nodebase + idx];
    }
    const int idx0 = __shfl_sync(0xffffffffu, idx, 0);
    const float s2v = g_s2[nodebase + idx0];
    if (lane < D) {
        e += s2v;
        e = (e >= 0.f) ? e : LRELU_ALPHA * e;
    }

    float m = e;
    #pragma unroll
    for (int o = 16; o > 0; o >>= 1) m = fmaxf(m, __shfl_xor_sync(0xffffffffu, m, o));
    float p = (lane < D) ? __expf(e - m) : 0.f;
    float s = p;
    #pragma unroll
    for (int o = 16; o > 0; o >>= 1) s += __shfl_xor_sync(0xffffffffu, s, o);
    const float attn = p / s;

    // gather: 8 x LDG.128 per warp (2 rows per iteration via half-warps)
    const int li = lane & 15;
    const int h  = lane >> 4;
    const __half* yb = g_yh + nodebase * F;
    float acc[8];
    #pragma unroll
    for (int j = 0; j < 8; j++) acc[j] = 0.f;

    #pragma unroll
    for (int it = 0; it < 8; it++) {
        const int   d  = 2 * it + h;
        const int   id = __shfl_sync(0xffffffffu, idx,  d);
        const float wt = __shfl_sync(0xffffffffu, attn, d);
        uint4 raw = *(const uint4*)(yb + (size_t)id * F + li * 8);
        const __half2* hh = reinterpret_cast<const __half2*>(&raw);
        #pragma unroll
        for (int j = 0; j < 4; j++) {
            float2 f2 = __half22float2(hh[j]);
            acc[2 * j]     += wt * f2.x;
            acc[2 * j + 1] += wt * f2.y;
        }
    }
    #pragma unroll
    for (int j = 0; j < 8; j++)
        acc[j] += __shfl_xor_sync(0xffffffffu, acc[j], 16);

    // elu (alpha=1) on the 4 values this lane writes: cols li*8 + h*4 + 0..3
    float4 o4;
    o4.x = acc[h * 4 + 0]; o4.y = acc[h * 4 + 1];
    o4.z = acc[h * 4 + 2]; o4.w = acc[h * 4 + 3];
    o4.x = o4.x > 0.f ? o4.x : (__expf(o4.x) - 1.f);
    o4.y = o4.y > 0.f ? o4.y : (__expf(o4.y) - 1.f);
    o4.z = o4.z > 0.f ? o4.z : (__expf(o4.z) - 1.f);
    o4.w = o4.w > 0.f ? o4.w : (__expf(o4.w) - 1.f);

    *(float4*)(out + (size_t)warp * F + li * 8 + h * 4) = o4;
}

// ---------------------------------------------------------------------------
extern "C" void kernel_launch(void* const* d_in, const int* in_sizes, int n_in,
                              void* d_out, int out_size)
{
    //   x: 10,240,000 f32 | adj: 1,280,000 (i32 or i64) | W: 16,384 f32 | a: 256 f32
    const float* x   = nullptr;
    const int*   adj = nullptr;
    const float* W   = nullptr;
    const float* a   = nullptr;
    for (int i = 0; i < n_in; i++) {
        switch (in_sizes[i]) {
            case NROWS * F: x   = (const float*)d_in[i]; break;
            case NROWS * D: adj = (const int*)d_in[i];   break;
            case F * F:     W   = (const float*)d_in[i]; break;
            case 2 * F:     a   = (const float*)d_in[i]; break;
            default: break;
        }
    }
    float* out = (float*)d_out;

    prep_kernel<<<32, 128>>>(adj, W);
    gemm_scores_kernel<<<NROWS / 64, 128>>>(x, a);
    attn_out_kernel<<<(NROWS * 32) / 256, 256>>>(adj, out);
}